// round 13
// baseline (speedup 1.0000x reference)
#include <cuda_runtime.h>
#include <cuda_fp16.h>

#define IN_DIM  1024
#define OUT_DIM 512
#define B_DIM   128
#define OT      16                  // output tile per block
#define ICH     32                  // input chunk per block
#define NSPLIT  (IN_DIM / ICH)      // 32 partials per (b,o)
#define NOUT    (B_DIM * OUT_DIM)   // 65536
#define NGRP    4                   // reduce stage-1 groups (8 splits each)

// Partial sums: [split][b][o]  (32 * 128 * 512 * 4B = 8 MB)
__device__ float g_part[NSPLIT * NOUT];
// Stage-1 partials: [group][b*512+o]  (1 MB)
__device__ float g_mid[NGRP * NOUT];

__device__ __forceinline__ float tanh_approx(float x) {
    float y;
    asm("tanh.approx.f32 %0, %1;" : "=f"(y) : "f"(x));
    return y;
}
__device__ __forceinline__ float rcp_approx(float x) {
    float y;
    asm("rcp.approx.f32 %0, %1;" : "=f"(y) : "f"(x));
    return y;
}
// Two tanhs in ONE MUFU instruction (sm_75+): halves the MUFU floor.
__device__ __forceinline__ unsigned tanh_h2(unsigned h2) {
    unsigned r;
    asm("tanh.approx.f16x2 %0, %1;" : "=r"(r) : "r"(h2));
    return r;
}
// Pack two f32 -> half2 (single cvt.rn.f16x2.f32).
__device__ __forceinline__ unsigned pack_h2(float lo, float hi) {
    unsigned r;
    asm("cvt.rn.f16x2.f32 %0, %2, %1;" : "=r"(r) : "f"(lo), "f"(hi));
    return r;
}
// Unpack half2 -> two f32.
__device__ __forceinline__ void unpack_h2(unsigned h2, float& lo, float& hi) {
    __half2 v = *reinterpret_cast<__half2*>(&h2);
    float2 f = __half22float2(v);
    lo = f.x; hi = f.y;
}

__device__ __forceinline__ float weff_one(float4 t, float w) {
    float a = __expf(t.x), b = __expf(t.y), c = __expf(t.z), d = __expf(t.w);
    float inv = rcp_approx(a + b + c + d);
    return (b * w + c * tanh_approx(w) + d * __sinf(w)) * inv;
}

// Fused kernel: each block owns (o-tile 16, i-chunk 32, ALL 128 batches).
// z = x*w computed in f32, pairs packed to half2, tanh via MUFU f16x2
// (2 elems/MUFU-op), accumulate in f32.
__global__ __launch_bounds__(256, 6)
void fbn_fused_kernel(const float* __restrict__ x,
                      const float* __restrict__ W,
                      const float* __restrict__ theta) {
    __shared__ float ws_t[ICH][OT];          // W_eff transposed [i][o], 2 KB
    __shared__ float xs[ICH][B_DIM];         // x transposed [i][b], 16 KB

    const int tid = threadIdx.x;
    const int o0 = blockIdx.x * OT;
    const int c0 = blockIdx.y * ICH;

    // ---- W_eff tile: 512 elements, 2 per thread ----
    {
        const float4* t4 = reinterpret_cast<const float4*>(theta);
        int m0 = tid, m1 = tid + 256;
        int ol0 = m0 >> 5, il0 = m0 & 31;
        int ol1 = m1 >> 5, il1 = m1 & 31;
        int g0 = (o0 + ol0) * IN_DIM + c0 + il0;
        int g1 = (o0 + ol1) * IN_DIM + c0 + il1;
        float4 ta = t4[g0];
        float4 tb = t4[g1];
        float wa = W[g0];
        float wb = W[g1];
        ws_t[il0][ol0] = weff_one(ta, wa);
        ws_t[il1][ol1] = weff_one(tb, wb);
    }

    // ---- x tile transposed: xs[i][b]; coalesced LDG.128, conflict-free STS ----
    {
        const float4* xg = reinterpret_cast<const float4*>(x);
        #pragma unroll
        for (int k = 0; k < 2; k++) {
            int f = tid + k * 256;          // 0..511
            int b = f & 127, i4 = f >> 7;   // i4 = 0..3 (group of 8 i's)
            float4 v0 = xg[b * (IN_DIM / 4) + (c0 >> 2) + i4 * 2];
            float4 v1 = xg[b * (IN_DIM / 4) + (c0 >> 2) + i4 * 2 + 1];
            xs[i4 * 8 + 0][b] = v0.x; xs[i4 * 8 + 1][b] = v0.y;
            xs[i4 * 8 + 2][b] = v0.z; xs[i4 * 8 + 3][b] = v0.w;
            xs[i4 * 8 + 4][b] = v1.x; xs[i4 * 8 + 5][b] = v1.y;
            xs[i4 * 8 + 6][b] = v1.z; xs[i4 * 8 + 7][b] = v1.w;
        }
    }
    __syncthreads();

    // ---- compute: thread = (o = tx, batches ty*8 .. ty*8+7) ----
    const int tx = tid & 15;
    const int ty = tid >> 4;
    const int bb = ty * 8;

    float acc0 = 0.f, acc1 = 0.f, acc2 = 0.f, acc3 = 0.f;
    float acc4 = 0.f, acc5 = 0.f, acc6 = 0.f, acc7 = 0.f;

    #pragma unroll 4
    for (int i = 0; i < ICH; i++) {
        float w = ws_t[i][tx];
        float4 xa = *reinterpret_cast<const float4*>(&xs[i][bb]);
        float4 xb = *reinterpret_cast<const float4*>(&xs[i][bb + 4]);
        // z in f32 (keeps f16 error to 2 quantizations)
        float z0 = xa.x * w, z1 = xa.y * w, z2 = xa.z * w, z3 = xa.w * w;
        float z4 = xb.x * w, z5 = xb.y * w, z6 = xb.z * w, z7 = xb.w * w;
        unsigned t01 = tanh_h2(pack_h2(z0, z1));
        unsigned t23 = tanh_h2(pack_h2(z2, z3));
        unsigned t45 = tanh_h2(pack_h2(z4, z5));
        unsigned t67 = tanh_h2(pack_h2(z6, z7));
        float f0, f1, f2, f3, f4, f5, f6, f7;
        unpack_h2(t01, f0, f1);
        unpack_h2(t23, f2, f3);
        unpack_h2(t45, f4, f5);
        unpack_h2(t67, f6, f7);
        acc0 += f0; acc1 += f1; acc2 += f2; acc3 += f3;
        acc4 += f4; acc5 += f5; acc6 += f6; acc7 += f7;
    }

    float* dst = g_part + (blockIdx.y * B_DIM + bb) * OUT_DIM + o0 + tx;
    dst[0 * OUT_DIM] = acc0;
    dst[1 * OUT_DIM] = acc1;
    dst[2 * OUT_DIM] = acc2;
    dst[3 * OUT_DIM] = acc3;
    dst[4 * OUT_DIM] = acc4;
    dst[5 * OUT_DIM] = acc5;
    dst[6 * OUT_DIM] = acc6;
    dst[7 * OUT_DIM] = acc7;
}

// Reduce stage 1: g_mid[g][idx] = sum of 8 splits. 256K threads -> latency
// hidden by occupancy.
__global__ __launch_bounds__(256)
void reduce1_kernel() {
    int t = blockIdx.x * blockDim.x + threadIdx.x;    // 0 .. 4*NOUT-1
    int idx = t & (NOUT - 1);
    int g = t >> 16;
    const float* p = g_part + g * 8 * NOUT + idx;
    float v0 = p[0 * NOUT], v1 = p[1 * NOUT], v2 = p[2 * NOUT], v3 = p[3 * NOUT];
    float v4 = p[4 * NOUT], v5 = p[5 * NOUT], v6 = p[6 * NOUT], v7 = p[7 * NOUT];
    v0 += v1; v2 += v3; v4 += v5; v6 += v7;
    g_mid[g * NOUT + idx] = (v0 + v2) + (v4 + v6);
}

// Reduce stage 2: out = bias + sum of 4 group sums.
__global__ __launch_bounds__(256)
void reduce2_kernel(const float* __restrict__ bias,
                    float* __restrict__ out) {
    int idx = blockIdx.x * blockDim.x + threadIdx.x;   // idx = b*512 + o
    float a = g_mid[0 * NOUT + idx];
    float b = g_mid[1 * NOUT + idx];
    float c = g_mid[2 * NOUT + idx];
    float d = g_mid[3 * NOUT + idx];
    out[idx] = bias[idx & (OUT_DIM - 1)] + ((a + b) + (c + d));
}

extern "C" void kernel_launch(void* const* d_in, const int* in_sizes, int n_in,
                              void* d_out, int out_size) {
    const float* x     = (const float*)d_in[0];   // (128, 1024)
    const float* W     = (const float*)d_in[1];   // (512, 1024)
    const float* bias  = (const float*)d_in[2];   // (512,)
    const float* theta = (const float*)d_in[3];   // (512, 1024, 4)
    float* out = (float*)d_out;                   // (128, 512)

    (void)in_sizes; (void)n_in; (void)out_size;

    dim3 grid(OUT_DIM / OT, IN_DIM / ICH);   // (32, 32) = 1024 blocks
    fbn_fused_kernel<<<grid, 256>>>(x, W, theta);

    reduce1_kernel<<<(NGRP * NOUT) / 256, 256>>>();
    reduce2_kernel<<<NOUT / 256, 256>>>(bias, out);
}

// round 14
// speedup vs baseline: 1.0164x; 1.0164x over previous
#include <cuda_runtime.h>
#include <cuda_fp16.h>

#define IN_DIM  1024
#define OUT_DIM 512
#define B_DIM   128
#define OPB     8                    // o's per block = warps per block
#define ICH     64                   // i-chunk per block
#define NSPLIT  (IN_DIM / ICH)       // 16
#define NOUT    (B_DIM * OUT_DIM)    // 65536
#define NGRP    4                    // reduce stage-1 groups (4 splits each)
#define XSTR    36                   // xs row stride in words: (4r+p)%32 conflict-free

// Partial sums: [split][o][b]  (16 * 512 * 128 * 4B = 4 MB)
__device__ float g_part[NSPLIT * NOUT];
// Stage-1 partials: [group][o*128+b]  (1 MB)
__device__ float g_mid[NGRP * NOUT];

__device__ __forceinline__ float tanh_approx(float x) {
    float y;
    asm("tanh.approx.f32 %0, %1;" : "=f"(y) : "f"(x));
    return y;
}
__device__ __forceinline__ float rcp_approx(float x) {
    float y;
    asm("rcp.approx.f32 %0, %1;" : "=f"(y) : "f"(x));
    return y;
}
// Two tanhs in ONE MUFU instruction.
__device__ __forceinline__ unsigned tanh_h2(unsigned h2) {
    unsigned r;
    asm("tanh.approx.f16x2 %0, %1;" : "=r"(r) : "r"(h2));
    return r;
}
// Pack two f32 -> half2 {lo, hi}.
__device__ __forceinline__ unsigned pack_h2(float lo, float hi) {
    unsigned r;
    asm("cvt.rn.f16x2.f32 %0, %2, %1;" : "=r"(r) : "f"(lo), "f"(hi));
    return r;
}
__device__ __forceinline__ unsigned hmul2u(unsigned a, unsigned b) {
    unsigned r;
    asm("mul.rn.f16x2 %0, %1, %2;" : "=r"(r) : "r"(a), "r"(b));
    return r;
}

// Fused kernel. Block = 8 warps; warp w owns output o0+w for ALL 128 batches
// over a 64-wide i-chunk.
//   1) warp computes its 64 W_eff values (f32), repacks to half2 pairs
//   2) block stages x as half2 pairs, layout xs[b][i-pair], stride 36 words
//   3) mainloop: per 16b x 16i tile -> HMUL2 (z, f16) -> tanh.f16x2 (MUFU)
//      -> mma.m16n8k16 with B=ones accumulates Sum_i tanh(z) in f32 on the
//      TENSOR pipe. No cvt/FADD on the XU pipe -> 0.5 MUFU-op/element.
__global__ __launch_bounds__(256, 7)
void fbn_fused_kernel(const float* __restrict__ x,
                      const float* __restrict__ W,
                      const float* __restrict__ theta) {
    __shared__ unsigned xs[B_DIM * XSTR];      // x half2 pairs, 18 KB
    __shared__ float    wsf[OPB][ICH];         // W_eff f32, 2 KB
    __shared__ unsigned wsh[OPB][ICH / 2];     // W_eff half2 pairs, 1 KB

    const int tid  = threadIdx.x;
    const int wid  = tid >> 5;
    const int lane = tid & 31;
    const int o0   = blockIdx.x * OPB;
    const int c0   = blockIdx.y * ICH;

    // ---- 1) W_eff for this warp's o: i = lane and lane+32 ----
    {
        const float4* t4 = reinterpret_cast<const float4*>(theta);
        int g0 = (o0 + wid) * IN_DIM + c0 + lane;
        int g1 = g0 + 32;
        float4 ta = t4[g0];
        float4 tb = t4[g1];
        float Wa = W[g0];
        float Wb = W[g1];
        float w0, w1;
        {
            float a = __expf(ta.x), b = __expf(ta.y), c = __expf(ta.z), d = __expf(ta.w);
            float inv = rcp_approx(a + b + c + d);
            w0 = (b * Wa + c * tanh_approx(Wa) + d * __sinf(Wa)) * inv;
        }
        {
            float a = __expf(tb.x), b = __expf(tb.y), c = __expf(tb.z), d = __expf(tb.w);
            float inv = rcp_approx(a + b + c + d);
            w1 = (b * Wb + c * tanh_approx(Wb) + d * __sinf(Wb)) * inv;
        }
        wsf[wid][lane]      = w0;
        wsf[wid][lane + 32] = w1;
    }
    __syncwarp();
    {
        float2 wv = *reinterpret_cast<const float2*>(&wsf[wid][lane * 2]);
        wsh[wid][lane] = pack_h2(wv.x, wv.y);
    }

    // ---- 2) x staging: half2 pairs, xs[b*XSTR + p] = {x[2p], x[2p+1]} ----
    {
        const float4* x4 = reinterpret_cast<const float4*>(x);
        #pragma unroll
        for (int k = 0; k < 8; k++) {
            int f = tid + k * 256;          // 0..2047
            int b = f >> 4, q = f & 15;     // q = float4 index within 64 i's
            float4 v = x4[b * (IN_DIM / 4) + (c0 >> 2) + q];
            unsigned p0 = pack_h2(v.x, v.y);
            unsigned p1 = pack_h2(v.z, v.w);
            *reinterpret_cast<uint2*>(&xs[b * XSTR + 2 * q]) = make_uint2(p0, p1);
        }
    }
    __syncthreads();

    // ---- 3) mainloop: 8 b-tiles x 4 k-subtiles of m16n8k16 ----
    const int gr = lane >> 2;        // row group 0..7
    const int cg = lane & 3;         // col group 0..3
    const unsigned ONES = 0x3C003C00u;   // half2 {1.0, 1.0}
    float* dst = g_part + (blockIdx.y * OUT_DIM + o0 + wid) * B_DIM;

    #pragma unroll
    for (int bt = 0; bt < 8; bt++) {
        const int r0 = bt * 16 + gr;
        const int r1 = r0 + 8;
        float d0 = 0.f, d1 = 0.f, d2 = 0.f, d3 = 0.f;
        #pragma unroll
        for (int ks = 0; ks < 4; ks++) {
            int pa = ks * 8 + cg;                      // pair index (cols 2pa,2pa+1)
            unsigned xa0 = xs[r0 * XSTR + pa];
            unsigned xa1 = xs[r1 * XSTR + pa];
            unsigned xa2 = xs[r0 * XSTR + pa + 4];
            unsigned xa3 = xs[r1 * XSTR + pa + 4];
            unsigned wA  = wsh[wid][pa];
            unsigned wB  = wsh[wid][pa + 4];
            unsigned a0 = tanh_h2(hmul2u(xa0, wA));
            unsigned a1 = tanh_h2(hmul2u(xa1, wA));
            unsigned a2 = tanh_h2(hmul2u(xa2, wB));
            unsigned a3 = tanh_h2(hmul2u(xa3, wB));
            asm volatile(
                "mma.sync.aligned.m16n8k16.row.col.f32.f16.f16.f32 "
                "{%0,%1,%2,%3}, {%4,%5,%6,%7}, {%8,%9}, {%0,%1,%2,%3};"
                : "+f"(d0), "+f"(d1), "+f"(d2), "+f"(d3)
                : "r"(a0), "r"(a1), "r"(a2), "r"(a3), "r"(ONES), "r"(ONES));
        }
        // D col 0 holds Sum_i tanh: lanes cg==0 own rows gr (d0) and gr+8 (d2).
        if (cg == 0) {
            dst[r0] = d0;
            dst[r1] = d2;
        }
    }
}

// Reduce stage 1: sum 4 splits per thread; 256K threads hide L2 latency.
__global__ __launch_bounds__(256)
void reduce1_kernel() {
    int t = blockIdx.x * blockDim.x + threadIdx.x;    // 0 .. 4*NOUT-1
    int idx = t & (NOUT - 1);
    int g = t >> 16;
    const float* p = g_part + g * 4 * NOUT + idx;
    float v0 = p[0 * NOUT], v1 = p[1 * NOUT], v2 = p[2 * NOUT], v3 = p[3 * NOUT];
    g_mid[g * NOUT + idx] = (v0 + v1) + (v2 + v3);
}

// Reduce stage 2: out[b][o] = bias[o] + sum of 4 group sums.
__global__ __launch_bounds__(256)
void reduce2_kernel(const float* __restrict__ bias,
                    float* __restrict__ out) {
    int idx = blockIdx.x * blockDim.x + threadIdx.x;   // idx = o*128 + b
    float a = g_mid[0 * NOUT + idx];
    float b = g_mid[1 * NOUT + idx];
    float c = g_mid[2 * NOUT + idx];
    float d = g_mid[3 * NOUT + idx];
    int o = idx >> 7, bi = idx & 127;
    out[bi * OUT_DIM + o] = bias[o] + ((a + b) + (c + d));
}

extern "C" void kernel_launch(void* const* d_in, const int* in_sizes, int n_in,
                              void* d_out, int out_size) {
    const float* x     = (const float*)d_in[0];   // (128, 1024)
    const float* W     = (const float*)d_in[1];   // (512, 1024)
    const float* bias  = (const float*)d_in[2];   // (512,)
    const float* theta = (const float*)d_in[3];   // (512, 1024, 4)
    float* out = (float*)d_out;                   // (128, 512)

    (void)in_sizes; (void)n_in; (void)out_size;

    dim3 grid(OUT_DIM / OPB, NSPLIT);   // (64, 16) = 1024 blocks, 1 wave @ 7/SM
    fbn_fused_kernel<<<grid, 256>>>(x, W, theta);

    reduce1_kernel<<<(NGRP * NOUT) / 256, 256>>>();
    reduce2_kernel<<<NOUT / 256, 256>>>(bias, out);
}

// round 15
// speedup vs baseline: 1.1410x; 1.1225x over previous
#include <cuda_runtime.h>
#include <cuda_fp16.h>

#define IN_DIM  1024
#define OUT_DIM 512
#define B_DIM   128
#define OPB     8                    // o's per block = warps per block
#define ICH     128                  // i-chunk per block (64 half2 pairs)
#define NPAIR   (ICH / 2)            // 64 pairs per warp
#define NSPLIT  (IN_DIM / ICH)       // 8
#define NOUT    (B_DIM * OUT_DIM)    // 65536
#define NGRP    2                    // reduce stage-1 groups (4 splits each)
#define XSTR    68                   // xs row stride in words (conflict-limited)
#define TAU_W   0.13f                // |w|<tau -> |z|<~0.56, deg-3 f16 poly ok

// Partial sums: [split][o][b]  (8 * 512 * 128 * 4B = 2 MB)
__device__ float g_part[NSPLIT * NOUT];
// Stage-1 partials: [group][o*128+b]  (0.5 MB)
__device__ float g_mid[NGRP * NOUT];

__device__ __forceinline__ float tanh_approx(float x) {
    float y;
    asm("tanh.approx.f32 %0, %1;" : "=f"(y) : "f"(x));
    return y;
}
__device__ __forceinline__ float rcp_approx(float x) {
    float y;
    asm("rcp.approx.f32 %0, %1;" : "=f"(y) : "f"(x));
    return y;
}
__device__ __forceinline__ unsigned tanh_h2(unsigned h2) {
    unsigned r;
    asm("tanh.approx.f16x2 %0, %1;" : "=r"(r) : "r"(h2));
    return r;
}
__device__ __forceinline__ unsigned pack_h2(float lo, float hi) {
    unsigned r;
    asm("cvt.rn.f16x2.f32 %0, %2, %1;" : "=r"(r) : "f"(lo), "f"(hi));
    return r;
}
__device__ __forceinline__ unsigned hmul2u(unsigned a, unsigned b) {
    unsigned r;
    asm("mul.rn.f16x2 %0, %1, %2;" : "=r"(r) : "r"(a), "r"(b));
    return r;
}
__device__ __forceinline__ unsigned hfma2u(unsigned a, unsigned b, unsigned c) {
    unsigned r;
    asm("fma.rn.f16x2 %0, %1, %2, %3;" : "=r"(r) : "r"(a), "r"(b), "r"(c));
    return r;
}

__device__ __forceinline__ float weff_one(float4 t, float w) {
    float a = __expf(t.x), b = __expf(t.y), c = __expf(t.z), d = __expf(t.w);
    float inv = rcp_approx(a + b + c + d);
    return (b * w + c * tanh_approx(w) + d * __sinf(w)) * inv;
}

// Fused hybrid kernel. Block = 8 warps; warp w owns output o0+w for all 128
// batches over a 128-wide i-chunk (64 half2 pairs).
//   1) warp computes its 128 W_eff (f32), packs to 64 half2 pairs, and
//      PARTITIONS pairs by |w|<TAU into poly-first order (ballot+prefix).
//      Permuting i is legal: sum over i is permutation-invariant, B=ones.
//   2) x staged as half2 pairs xs[b][pair]
//   3) mainloop over 8 k-chunks of 8 pairs: chunks [0,npc) are all-poly
//      (deg-3 HFMA2 on the FMA pipe), chunks [npc,8) use tanh.f16x2 (MUFU).
//      Products accumulate in f32 via mma.m16n8k16 with B=ones (tensor pipe).
__global__ __launch_bounds__(256)
void fbn_fused_kernel(const float* __restrict__ x,
                      const float* __restrict__ W,
                      const float* __restrict__ theta) {
    __shared__ unsigned xs[B_DIM * XSTR];       // x half2 pairs, 34 KB
    __shared__ unsigned wshp[OPB][NPAIR];       // permuted w half2, 2 KB
    __shared__ int      xoffp[OPB][NPAIR];      // permuted pair index, 2 KB

    const int tid  = threadIdx.x;
    const int wid  = tid >> 5;
    const int lane = tid & 31;
    const int o0   = blockIdx.x * OPB;
    const int c0   = blockIdx.y * ICH;

    // ---- 1) W_eff pairs + partition. Lane owns pairs p=lane and p=lane+32.
    int npc;
    {
        const float4*  t4 = reinterpret_cast<const float4*>(theta);
        const float2*  W2 = reinterpret_cast<const float2*>(W);
        int base = (o0 + wid) * IN_DIM + c0;
        float4 ta0 = t4[base + 2 * lane];
        float4 ta1 = t4[base + 2 * lane + 1];
        float4 tb0 = t4[base + 64 + 2 * lane];
        float4 tb1 = t4[base + 64 + 2 * lane + 1];
        float2 Wa = W2[(base >> 1) + lane];
        float2 Wb = W2[(base >> 1) + 32 + lane];
        float w00 = weff_one(ta0, Wa.x);
        float w01 = weff_one(ta1, Wa.y);
        float w10 = weff_one(tb0, Wb.x);
        float w11 = weff_one(tb1, Wb.y);

        bool s0 = fmaxf(fabsf(w00), fabsf(w01)) < TAU_W;
        bool s1 = fmaxf(fabsf(w10), fabsf(w11)) < TAU_W;
        unsigned m0 = __ballot_sync(0xffffffffu, s0);
        unsigned m1 = __ballot_sync(0xffffffffu, s1);
        int n0 = __popc(m0);
        int np = n0 + __popc(m1);
        unsigned lt = (1u << lane) - 1u;
        int p0 = s0 ? __popc(m0 & lt)
                    : np + __popc(~m0 & lt);
        int p1 = s1 ? n0 + __popc(m1 & lt)
                    : np + __popc(~m0) + __popc(~m1 & lt);
        wshp[wid][p0] = pack_h2(w00, w01);  xoffp[wid][p0] = lane;
        wshp[wid][p1] = pack_h2(w10, w11);  xoffp[wid][p1] = lane + 32;
        npc = np >> 3;    // number of all-poly 8-pair chunks
    }

    // ---- 2) x staging: xs[b*XSTR + p] = half2 {x[2p], x[2p+1]} ----
    {
        const float4* x4 = reinterpret_cast<const float4*>(x);
        #pragma unroll
        for (int k = 0; k < 16; k++) {
            int f = tid + k * 256;          // 0..4095
            int b = f >> 5, q = f & 31;     // q = float4 index within 128 i's
            float4 v = x4[b * (IN_DIM / 4) + (c0 >> 2) + q];
            xs[b * XSTR + 2 * q]     = pack_h2(v.x, v.y);
            xs[b * XSTR + 2 * q + 1] = pack_h2(v.z, v.w);
        }
    }
    __syncthreads();

    // ---- 3) mainloop ----
    const int gr = lane >> 2;        // A-fragment row group 0..7
    const int cg = lane & 3;         // A-fragment col group 0..3
    const unsigned ONES = 0x3C003C00u;   // half2 {1, 1}
    const unsigned C3H2 = 0xB555B555u;   // half2 {-1/3, -1/3}
    float* dst = g_part + (blockIdx.y * OUT_DIM + o0 + wid) * B_DIM;

    #pragma unroll
    for (int btg = 0; btg < 2; btg++) {     // 2 groups of 4 b-tiles
        const int rb = btg * 64;
        float d0[4] = {0.f, 0.f, 0.f, 0.f};
        float d1[4] = {0.f, 0.f, 0.f, 0.f};
        float d2[4] = {0.f, 0.f, 0.f, 0.f};
        float d3[4] = {0.f, 0.f, 0.f, 0.f};

        // Poly chunks (FMA pipe): tanh(z) ~= z * (1 - z^2/3)
        for (int ks = 0; ks < npc; ks++) {
            unsigned wA = wshp[wid][ks * 8 + cg];
            unsigned wB = wshp[wid][ks * 8 + cg + 4];
            int pA = xoffp[wid][ks * 8 + cg];
            int pB = xoffp[wid][ks * 8 + cg + 4];
            #pragma unroll
            for (int bt = 0; bt < 4; bt++) {
                int r0 = (rb + bt * 16 + gr) * XSTR;
                int r1 = r0 + 8 * XSTR;
                unsigned z0 = hmul2u(xs[r0 + pA], wA);
                unsigned z1 = hmul2u(xs[r1 + pA], wA);
                unsigned z2 = hmul2u(xs[r0 + pB], wB);
                unsigned z3 = hmul2u(xs[r1 + pB], wB);
                unsigned a0 = hmul2u(z0, hfma2u(hmul2u(z0, z0), C3H2, ONES));
                unsigned a1 = hmul2u(z1, hfma2u(hmul2u(z1, z1), C3H2, ONES));
                unsigned a2 = hmul2u(z2, hfma2u(hmul2u(z2, z2), C3H2, ONES));
                unsigned a3 = hmul2u(z3, hfma2u(hmul2u(z3, z3), C3H2, ONES));
                asm volatile(
                    "mma.sync.aligned.m16n8k16.row.col.f32.f16.f16.f32 "
                    "{%0,%1,%2,%3}, {%4,%5,%6,%7}, {%8,%9}, {%0,%1,%2,%3};"
                    : "+f"(d0[bt]), "+f"(d1[bt]), "+f"(d2[bt]), "+f"(d3[bt])
                    : "r"(a0), "r"(a1), "r"(a2), "r"(a3), "r"(ONES), "r"(ONES));
            }
        }
        // Mufu chunks (MUFU pipe): hardware tanh (handles any |w|, incl.
        // the mixed boundary chunk)
        for (int ks = npc; ks < 8; ks++) {
            unsigned wA = wshp[wid][ks * 8 + cg];
            unsigned wB = wshp[wid][ks * 8 + cg + 4];
            int pA = xoffp[wid][ks * 8 + cg];
            int pB = xoffp[wid][ks * 8 + cg + 4];
            #pragma unroll
            for (int bt = 0; bt < 4; bt++) {
                int r0 = (rb + bt * 16 + gr) * XSTR;
                int r1 = r0 + 8 * XSTR;
                unsigned a0 = tanh_h2(hmul2u(xs[r0 + pA], wA));
                unsigned a1 = tanh_h2(hmul2u(xs[r1 + pA], wA));
                unsigned a2 = tanh_h2(hmul2u(xs[r0 + pB], wB));
                unsigned a3 = tanh_h2(hmul2u(xs[r1 + pB], wB));
                asm volatile(
                    "mma.sync.aligned.m16n8k16.row.col.f32.f16.f16.f32 "
                    "{%0,%1,%2,%3}, {%4,%5,%6,%7}, {%8,%9}, {%0,%1,%2,%3};"
                    : "+f"(d0[bt]), "+f"(d1[bt]), "+f"(d2[bt]), "+f"(d3[bt])
                    : "r"(a0), "r"(a1), "r"(a2), "r"(a3), "r"(ONES), "r"(ONES));
            }
        }

        // D column 0: lanes with cg==0 hold rows gr (d0) and gr+8 (d2).
        if (cg == 0) {
            #pragma unroll
            for (int bt = 0; bt < 4; bt++) {
                dst[rb + bt * 16 + gr]     = d0[bt];
                dst[rb + bt * 16 + gr + 8] = d2[bt];
            }
        }
    }
}

// Reduce stage 1: sum 4 splits per thread; 128K threads hide L2 latency.
__global__ __launch_bounds__(256)
void reduce1_kernel() {
    int t = blockIdx.x * blockDim.x + threadIdx.x;    // 0 .. 2*NOUT-1
    int idx = t & (NOUT - 1);
    int g = t >> 16;
    const float* p = g_part + g * 4 * NOUT + idx;
    float v0 = p[0 * NOUT], v1 = p[1 * NOUT], v2 = p[2 * NOUT], v3 = p[3 * NOUT];
    g_mid[g * NOUT + idx] = (v0 + v1) + (v2 + v3);
}

// Reduce stage 2: out[b][o] = bias[o] + two group sums.
__global__ __launch_bounds__(256)
void reduce2_kernel(const float* __restrict__ bias,
                    float* __restrict__ out) {
    int idx = blockIdx.x * blockDim.x + threadIdx.x;   // idx = o*128 + b
    float a = g_mid[idx];
    float b = g_mid[NOUT + idx];
    int o = idx >> 7, bi = idx & 127;
    out[bi * OUT_DIM + o] = bias[o] + a + b;
}

extern "C" void kernel_launch(void* const* d_in, const int* in_sizes, int n_in,
                              void* d_out, int out_size) {
    const float* x     = (const float*)d_in[0];   // (128, 1024)
    const float* W     = (const float*)d_in[1];   // (512, 1024)
    const float* bias  = (const float*)d_in[2];   // (512,)
    const float* theta = (const float*)d_in[3];   // (512, 1024, 4)
    float* out = (float*)d_out;                   // (128, 512)

    (void)in_sizes; (void)n_in; (void)out_size;

    dim3 grid(OUT_DIM / OPB, NSPLIT);   // (64, 8) = 512 blocks
    fbn_fused_kernel<<<grid, 256>>>(x, W, theta);

    reduce1_kernel<<<(NGRP * NOUT) / 256, 256>>>();
    reduce2_kernel<<<NOUT / 256, 256>>>(bias, out);
}

// round 16
// speedup vs baseline: 1.2180x; 1.0675x over previous
#include <cuda_runtime.h>
#include <cuda_fp16.h>

#define IN_DIM  1024
#define OUT_DIM 512
#define B_DIM   128
#define B_LOC   64                   // batches per block (z-split)
#define OPB     8                    // o's per block = warps per block
#define ICH     128                  // i-chunk per block (64 half2 pairs)
#define NPAIR   (ICH / 2)            // 64 pairs per warp
#define NSPLIT  (IN_DIM / ICH)       // 8
#define NOUT    (B_DIM * OUT_DIM)    // 65536
#define NGRP    2                    // reduce stage-1 groups (4 splits each)
#define XSTR    68                   // xs row stride in words
#define TAU_W   0.13f                // |w|<tau -> |z|<~0.56, deg-3 f16 poly ok

// Partial sums: [split][o][b]  (8 * 512 * 128 * 4B = 2 MB)
__device__ float g_part[NSPLIT * NOUT];
// Stage-1 partials: [group][o*128+b]  (0.5 MB)
__device__ float g_mid[NGRP * NOUT];

__device__ __forceinline__ float tanh_approx(float x) {
    float y;
    asm("tanh.approx.f32 %0, %1;" : "=f"(y) : "f"(x));
    return y;
}
__device__ __forceinline__ float rcp_approx(float x) {
    float y;
    asm("rcp.approx.f32 %0, %1;" : "=f"(y) : "f"(x));
    return y;
}
__device__ __forceinline__ unsigned tanh_h2(unsigned h2) {
    unsigned r;
    asm("tanh.approx.f16x2 %0, %1;" : "=r"(r) : "r"(h2));
    return r;
}
__device__ __forceinline__ unsigned pack_h2(float lo, float hi) {
    unsigned r;
    asm("cvt.rn.f16x2.f32 %0, %2, %1;" : "=r"(r) : "f"(lo), "f"(hi));
    return r;
}
__device__ __forceinline__ unsigned hmul2u(unsigned a, unsigned b) {
    unsigned r;
    asm("mul.rn.f16x2 %0, %1, %2;" : "=r"(r) : "r"(a), "r"(b));
    return r;
}
__device__ __forceinline__ unsigned hfma2u(unsigned a, unsigned b, unsigned c) {
    unsigned r;
    asm("fma.rn.f16x2 %0, %1, %2, %3;" : "=r"(r) : "r"(a), "r"(b), "r"(c));
    return r;
}

__device__ __forceinline__ float weff_one(float4 t, float w) {
    float a = __expf(t.x), b = __expf(t.y), c = __expf(t.z), d = __expf(t.w);
    float inv = rcp_approx(a + b + c + d);
    return (b * w + c * tanh_approx(w) + d * __sinf(w)) * inv;
}

// Fused hybrid kernel. Block = 8 warps; warp w owns output o0+w for 64
// batches (z-half) over a 128-wide i-chunk (64 half2 pairs).
// Same math as R15 (validated rel_err 5.9e-4); grid doubled via batch split
// for occupancy. Both z-halves compute identical W_eff (deterministic).
__global__ __launch_bounds__(256)
void fbn_fused_kernel(const float* __restrict__ x,
                      const float* __restrict__ W,
                      const float* __restrict__ theta) {
    __shared__ unsigned xs[B_LOC * XSTR];       // x half2 pairs, 17.4 KB
    __shared__ unsigned wshp[OPB][NPAIR];       // permuted w half2, 2 KB
    __shared__ int      xoffp[OPB][NPAIR];      // permuted pair index, 2 KB

    const int tid  = threadIdx.x;
    const int wid  = tid >> 5;
    const int lane = tid & 31;
    const int o0   = blockIdx.x * OPB;
    const int c0   = blockIdx.y * ICH;
    const int bz   = blockIdx.z * B_LOC;

    // ---- 1) W_eff pairs + partition (per warp, poly-first order) ----
    int npc;
    {
        const float4*  t4 = reinterpret_cast<const float4*>(theta);
        const float2*  W2 = reinterpret_cast<const float2*>(W);
        int base = (o0 + wid) * IN_DIM + c0;
        float4 ta0 = t4[base + 2 * lane];
        float4 ta1 = t4[base + 2 * lane + 1];
        float4 tb0 = t4[base + 64 + 2 * lane];
        float4 tb1 = t4[base + 64 + 2 * lane + 1];
        float2 Wa = W2[(base >> 1) + lane];
        float2 Wb = W2[(base >> 1) + 32 + lane];
        float w00 = weff_one(ta0, Wa.x);
        float w01 = weff_one(ta1, Wa.y);
        float w10 = weff_one(tb0, Wb.x);
        float w11 = weff_one(tb1, Wb.y);

        bool s0 = fmaxf(fabsf(w00), fabsf(w01)) < TAU_W;
        bool s1 = fmaxf(fabsf(w10), fabsf(w11)) < TAU_W;
        unsigned m0 = __ballot_sync(0xffffffffu, s0);
        unsigned m1 = __ballot_sync(0xffffffffu, s1);
        int n0 = __popc(m0);
        int np = n0 + __popc(m1);
        unsigned lt = (1u << lane) - 1u;
        int p0 = s0 ? __popc(m0 & lt)
                    : np + __popc(~m0 & lt);
        int p1 = s1 ? n0 + __popc(m1 & lt)
                    : np + __popc(~m0) + __popc(~m1 & lt);
        wshp[wid][p0] = pack_h2(w00, w01);  xoffp[wid][p0] = lane;
        wshp[wid][p1] = pack_h2(w10, w11);  xoffp[wid][p1] = lane + 32;
        npc = np >> 3;    // number of all-poly 8-pair chunks
    }

    // ---- 2) x staging: 64 local batches, xs[b*XSTR + p] = {x[2p],x[2p+1]} ----
    {
        const float4* x4 = reinterpret_cast<const float4*>(x);
        #pragma unroll
        for (int k = 0; k < 8; k++) {
            int f = tid + k * 256;          // 0..2047
            int b = f >> 5, q = f & 31;     // b local 0..63
            float4 v = x4[(bz + b) * (IN_DIM / 4) + (c0 >> 2) + q];
            xs[b * XSTR + 2 * q]     = pack_h2(v.x, v.y);
            xs[b * XSTR + 2 * q + 1] = pack_h2(v.z, v.w);
        }
    }
    __syncthreads();

    // ---- 3) mainloop: 4 b-tiles x 8 k-chunks of m16n8k16 ----
    const int gr = lane >> 2;        // A-fragment row group 0..7
    const int cg = lane & 3;         // A-fragment col group 0..3
    const unsigned ONES = 0x3C003C00u;   // half2 {1, 1}
    const unsigned C3H2 = 0xB555B555u;   // half2 {-1/3, -1/3}
    float* dst = g_part + (blockIdx.y * OUT_DIM + o0 + wid) * B_DIM + bz;

    float d0[4] = {0.f, 0.f, 0.f, 0.f};
    float d1[4] = {0.f, 0.f, 0.f, 0.f};
    float d2[4] = {0.f, 0.f, 0.f, 0.f};
    float d3[4] = {0.f, 0.f, 0.f, 0.f};

    // Poly chunks (FMA pipe): tanh(z) ~= z * (1 - z^2/3)
    for (int ks = 0; ks < npc; ks++) {
        unsigned wA = wshp[wid][ks * 8 + cg];
        unsigned wB = wshp[wid][ks * 8 + cg + 4];
        int pA = xoffp[wid][ks * 8 + cg];
        int pB = xoffp[wid][ks * 8 + cg + 4];
        #pragma unroll
        for (int bt = 0; bt < 4; bt++) {
            int r0 = (bt * 16 + gr) * XSTR;
            int r1 = r0 + 8 * XSTR;
            unsigned z0 = hmul2u(xs[r0 + pA], wA);
            unsigned z1 = hmul2u(xs[r1 + pA], wA);
            unsigned z2 = hmul2u(xs[r0 + pB], wB);
            unsigned z3 = hmul2u(xs[r1 + pB], wB);
            unsigned a0 = hmul2u(z0, hfma2u(hmul2u(z0, z0), C3H2, ONES));
            unsigned a1 = hmul2u(z1, hfma2u(hmul2u(z1, z1), C3H2, ONES));
            unsigned a2 = hmul2u(z2, hfma2u(hmul2u(z2, z2), C3H2, ONES));
            unsigned a3 = hmul2u(z3, hfma2u(hmul2u(z3, z3), C3H2, ONES));
            asm volatile(
                "mma.sync.aligned.m16n8k16.row.col.f32.f16.f16.f32 "
                "{%0,%1,%2,%3}, {%4,%5,%6,%7}, {%8,%9}, {%0,%1,%2,%3};"
                : "+f"(d0[bt]), "+f"(d1[bt]), "+f"(d2[bt]), "+f"(d3[bt])
                : "r"(a0), "r"(a1), "r"(a2), "r"(a3), "r"(ONES), "r"(ONES));
        }
    }
    // Mufu chunks (MUFU pipe): hardware tanh (incl. mixed boundary chunk)
    for (int ks = npc; ks < 8; ks++) {
        unsigned wA = wshp[wid][ks * 8 + cg];
        unsigned wB = wshp[wid][ks * 8 + cg + 4];
        int pA = xoffp[wid][ks * 8 + cg];
        int pB = xoffp[wid][ks * 8 + cg + 4];
        #pragma unroll
        for (int bt = 0; bt < 4; bt++) {
            int r0 = (bt * 16 + gr) * XSTR;
            int r1 = r0 + 8 * XSTR;
            unsigned a0 = tanh_h2(hmul2u(xs[r0 + pA], wA));
            unsigned a1 = tanh_h2(hmul2u(xs[r1 + pA], wA));
            unsigned a2 = tanh_h2(hmul2u(xs[r0 + pB], wB));
            unsigned a3 = tanh_h2(hmul2u(xs[r1 + pB], wB));
            asm volatile(
                "mma.sync.aligned.m16n8k16.row.col.f32.f16.f16.f32 "
                "{%0,%1,%2,%3}, {%4,%5,%6,%7}, {%8,%9}, {%0,%1,%2,%3};"
                : "+f"(d0[bt]), "+f"(d1[bt]), "+f"(d2[bt]), "+f"(d3[bt])
                : "r"(a0), "r"(a1), "r"(a2), "r"(a3), "r"(ONES), "r"(ONES));
        }
    }

    // D column 0: lanes with cg==0 hold rows gr (d0) and gr+8 (d2).
    if (cg == 0) {
        #pragma unroll
        for (int bt = 0; bt < 4; bt++) {
            dst[bt * 16 + gr]     = d0[bt];
            dst[bt * 16 + gr + 8] = d2[bt];
        }
    }
}

// Reduce stage 1: sum 4 splits per thread; 128K threads hide L2 latency.
__global__ __launch_bounds__(256)
void reduce1_kernel() {
    int t = blockIdx.x * blockDim.x + threadIdx.x;    // 0 .. 2*NOUT-1
    int idx = t & (NOUT - 1);
    int g = t >> 16;
    const float* p = g_part + g * 4 * NOUT + idx;
    float v0 = p[0 * NOUT], v1 = p[1 * NOUT], v2 = p[2 * NOUT], v3 = p[3 * NOUT];
    g_mid[g * NOUT + idx] = (v0 + v1) + (v2 + v3);
}

// Reduce stage 2: out[b][o] = bias[o] + two group sums.
__global__ __launch_bounds__(256)
void reduce2_kernel(const float* __restrict__ bias,
                    float* __restrict__ out) {
    int idx = blockIdx.x * blockDim.x + threadIdx.x;   // idx = o*128 + b
    float a = g_mid[idx];
    float b = g_mid[NOUT + idx];
    int o = idx >> 7, bi = idx & 127;
    out[bi * OUT_DIM + o] = bias[o] + a + b;
}

extern "C" void kernel_launch(void* const* d_in, const int* in_sizes, int n_in,
                              void* d_out, int out_size) {
    const float* x     = (const float*)d_in[0];   // (128, 1024)
    const float* W     = (const float*)d_in[1];   // (512, 1024)
    const float* bias  = (const float*)d_in[2];   // (512,)
    const float* theta = (const float*)d_in[3];   // (512, 1024, 4)
    float* out = (float*)d_out;                   // (128, 512)

    (void)in_sizes; (void)n_in; (void)out_size;

    dim3 grid(OUT_DIM / OPB, NSPLIT, 2);   // (64, 8, 2) = 1024 blocks
    fbn_fused_kernel<<<grid, 256>>>(x, W, theta);

    reduce1_kernel<<<(NGRP * NOUT) / 256, 256>>>();
    reduce2_kernel<<<NOUT / 256, 256>>>(bias, out);
}

// round 17
// speedup vs baseline: 1.3468x; 1.1058x over previous
#include <cuda_runtime.h>
#include <cuda_fp16.h>

#define IN_DIM  1024
#define OUT_DIM 512
#define B_DIM   128
#define B_LOC   64                   // batches per block (z-split)
#define OPB     8                    // o's per block = warps per block
#define ICH     128                  // i-chunk per block (64 half2 pairs)
#define NPAIR   (ICH / 2)            // 64 pairs per warp
#define NSPLIT  (IN_DIM / ICH)       // 8
#define NOUT    (B_DIM * OUT_DIM)    // 65536
#define XSTR    68                   // xs row stride in words
#define TAU_W   0.13f                // |w|<tau -> |z|<~0.56, deg-3 f16 poly ok

// Partial sums: [split][o][b]  (8 * 512 * 128 * 4B = 2 MB)
__device__ float g_part[NSPLIT * NOUT];

__device__ __forceinline__ float tanh_approx(float x) {
    float y;
    asm("tanh.approx.f32 %0, %1;" : "=f"(y) : "f"(x));
    return y;
}
__device__ __forceinline__ float rcp_approx(float x) {
    float y;
    asm("rcp.approx.f32 %0, %1;" : "=f"(y) : "f"(x));
    return y;
}
__device__ __forceinline__ unsigned tanh_h2(unsigned h2) {
    unsigned r;
    asm("tanh.approx.f16x2 %0, %1;" : "=r"(r) : "r"(h2));
    return r;
}
__device__ __forceinline__ unsigned pack_h2(float lo, float hi) {
    unsigned r;
    asm("cvt.rn.f16x2.f32 %0, %2, %1;" : "=r"(r) : "f"(lo), "f"(hi));
    return r;
}
__device__ __forceinline__ unsigned hmul2u(unsigned a, unsigned b) {
    unsigned r;
    asm("mul.rn.f16x2 %0, %1, %2;" : "=r"(r) : "r"(a), "r"(b));
    return r;
}
__device__ __forceinline__ unsigned hfma2u(unsigned a, unsigned b, unsigned c) {
    unsigned r;
    asm("fma.rn.f16x2 %0, %1, %2, %3;" : "=r"(r) : "r"(a), "r"(b), "r"(c));
    return r;
}

__device__ __forceinline__ float weff_one(float4 t, float w) {
    float a = __expf(t.x), b = __expf(t.y), c = __expf(t.z), d = __expf(t.w);
    float inv = rcp_approx(a + b + c + d);
    return (b * w + c * tanh_approx(w) + d * __sinf(w)) * inv;
}

// Fused hybrid kernel — byte-identical to R16 (passing, fused 18.6us,
// rel_err 5.9e-4). Block = 8 warps; warp w owns output o0+w for 64 batches
// (z-half) over a 128-wide i-chunk (64 half2 pairs).
__global__ __launch_bounds__(256)
void fbn_fused_kernel(const float* __restrict__ x,
                      const float* __restrict__ W,
                      const float* __restrict__ theta) {
    __shared__ unsigned xs[B_LOC * XSTR];       // x half2 pairs, 17.4 KB
    __shared__ unsigned wshp[OPB][NPAIR];       // permuted w half2, 2 KB
    __shared__ int      xoffp[OPB][NPAIR];      // permuted pair index, 2 KB

    const int tid  = threadIdx.x;
    const int wid  = tid >> 5;
    const int lane = tid & 31;
    const int o0   = blockIdx.x * OPB;
    const int c0   = blockIdx.y * ICH;
    const int bz   = blockIdx.z * B_LOC;

    // ---- 1) W_eff pairs + partition (per warp, poly-first order) ----
    int npc;
    {
        const float4*  t4 = reinterpret_cast<const float4*>(theta);
        const float2*  W2 = reinterpret_cast<const float2*>(W);
        int base = (o0 + wid) * IN_DIM + c0;
        float4 ta0 = t4[base + 2 * lane];
        float4 ta1 = t4[base + 2 * lane + 1];
        float4 tb0 = t4[base + 64 + 2 * lane];
        float4 tb1 = t4[base + 64 + 2 * lane + 1];
        float2 Wa = W2[(base >> 1) + lane];
        float2 Wb = W2[(base >> 1) + 32 + lane];
        float w00 = weff_one(ta0, Wa.x);
        float w01 = weff_one(ta1, Wa.y);
        float w10 = weff_one(tb0, Wb.x);
        float w11 = weff_one(tb1, Wb.y);

        bool s0 = fmaxf(fabsf(w00), fabsf(w01)) < TAU_W;
        bool s1 = fmaxf(fabsf(w10), fabsf(w11)) < TAU_W;
        unsigned m0 = __ballot_sync(0xffffffffu, s0);
        unsigned m1 = __ballot_sync(0xffffffffu, s1);
        int n0 = __popc(m0);
        int np = n0 + __popc(m1);
        unsigned lt = (1u << lane) - 1u;
        int p0 = s0 ? __popc(m0 & lt)
                    : np + __popc(~m0 & lt);
        int p1 = s1 ? n0 + __popc(m1 & lt)
                    : np + __popc(~m0) + __popc(~m1 & lt);
        wshp[wid][p0] = pack_h2(w00, w01);  xoffp[wid][p0] = lane;
        wshp[wid][p1] = pack_h2(w10, w11);  xoffp[wid][p1] = lane + 32;
        npc = np >> 3;    // number of all-poly 8-pair chunks
    }

    // ---- 2) x staging: 64 local batches, xs[b*XSTR + p] = {x[2p],x[2p+1]} ----
    {
        const float4* x4 = reinterpret_cast<const float4*>(x);
        #pragma unroll
        for (int k = 0; k < 8; k++) {
            int f = tid + k * 256;          // 0..2047
            int b = f >> 5, q = f & 31;     // b local 0..63
            float4 v = x4[(bz + b) * (IN_DIM / 4) + (c0 >> 2) + q];
            xs[b * XSTR + 2 * q]     = pack_h2(v.x, v.y);
            xs[b * XSTR + 2 * q + 1] = pack_h2(v.z, v.w);
        }
    }
    __syncthreads();

    // ---- 3) mainloop: 4 b-tiles x 8 k-chunks of m16n8k16 ----
    const int gr = lane >> 2;        // A-fragment row group 0..7
    const int cg = lane & 3;         // A-fragment col group 0..3
    const unsigned ONES = 0x3C003C00u;   // half2 {1, 1}
    const unsigned C3H2 = 0xB555B555u;   // half2 {-1/3, -1/3}
    float* dst = g_part + (blockIdx.y * OUT_DIM + o0 + wid) * B_DIM + bz;

    float d0[4] = {0.f, 0.f, 0.f, 0.f};
    float d1[4] = {0.f, 0.f, 0.f, 0.f};
    float d2[4] = {0.f, 0.f, 0.f, 0.f};
    float d3[4] = {0.f, 0.f, 0.f, 0.f};

    // Poly chunks (FMA pipe): tanh(z) ~= z * (1 - z^2/3)
    for (int ks = 0; ks < npc; ks++) {
        unsigned wA = wshp[wid][ks * 8 + cg];
        unsigned wB = wshp[wid][ks * 8 + cg + 4];
        int pA = xoffp[wid][ks * 8 + cg];
        int pB = xoffp[wid][ks * 8 + cg + 4];
        #pragma unroll
        for (int bt = 0; bt < 4; bt++) {
            int r0 = (bt * 16 + gr) * XSTR;
            int r1 = r0 + 8 * XSTR;
            unsigned z0 = hmul2u(xs[r0 + pA], wA);
            unsigned z1 = hmul2u(xs[r1 + pA], wA);
            unsigned z2 = hmul2u(xs[r0 + pB], wB);
            unsigned z3 = hmul2u(xs[r1 + pB], wB);
            unsigned a0 = hmul2u(z0, hfma2u(hmul2u(z0, z0), C3H2, ONES));
            unsigned a1 = hmul2u(z1, hfma2u(hmul2u(z1, z1), C3H2, ONES));
            unsigned a2 = hmul2u(z2, hfma2u(hmul2u(z2, z2), C3H2, ONES));
            unsigned a3 = hmul2u(z3, hfma2u(hmul2u(z3, z3), C3H2, ONES));
            asm volatile(
                "mma.sync.aligned.m16n8k16.row.col.f32.f16.f16.f32 "
                "{%0,%1,%2,%3}, {%4,%5,%6,%7}, {%8,%9}, {%0,%1,%2,%3};"
                : "+f"(d0[bt]), "+f"(d1[bt]), "+f"(d2[bt]), "+f"(d3[bt])
                : "r"(a0), "r"(a1), "r"(a2), "r"(a3), "r"(ONES), "r"(ONES));
        }
    }
    // Mufu chunks (MUFU pipe): hardware tanh (incl. mixed boundary chunk)
    for (int ks = npc; ks < 8; ks++) {
        unsigned wA = wshp[wid][ks * 8 + cg];
        unsigned wB = wshp[wid][ks * 8 + cg + 4];
        int pA = xoffp[wid][ks * 8 + cg];
        int pB = xoffp[wid][ks * 8 + cg + 4];
        #pragma unroll
        for (int bt = 0; bt < 4; bt++) {
            int r0 = (bt * 16 + gr) * XSTR;
            int r1 = r0 + 8 * XSTR;
            unsigned a0 = tanh_h2(hmul2u(xs[r0 + pA], wA));
            unsigned a1 = tanh_h2(hmul2u(xs[r1 + pA], wA));
            unsigned a2 = tanh_h2(hmul2u(xs[r0 + pB], wB));
            unsigned a3 = tanh_h2(hmul2u(xs[r1 + pB], wB));
            asm volatile(
                "mma.sync.aligned.m16n8k16.row.col.f32.f16.f16.f32 "
                "{%0,%1,%2,%3}, {%4,%5,%6,%7}, {%8,%9}, {%0,%1,%2,%3};"
                : "+f"(d0[bt]), "+f"(d1[bt]), "+f"(d2[bt]), "+f"(d3[bt])
                : "r"(a0), "r"(a1), "r"(a2), "r"(a3), "r"(ONES), "r"(ONES));
        }
    }

    // D column 0: lanes with cg==0 hold rows gr (d0) and gr+8 (d2).
    if (cg == 0) {
        #pragma unroll
        for (int bt = 0; bt < 4; bt++) {
            dst[bt * 16 + gr]     = d0[bt];
            dst[bt * 16 + gr + 8] = d2[bt];
        }
    }
}

// Single-stage reduce: 128K threads. Thread t handles output idx = t>>1,
// half g = t&1: sums splits [g*4, g*4+4), then lane-pair shfl combines the
// two halves. Deterministic (fixed tree), one launch, no mid buffer.
__global__ __launch_bounds__(256)
void reduce_kernel(const float* __restrict__ bias,
                   float* __restrict__ out) {
    int t = blockIdx.x * blockDim.x + threadIdx.x;    // 0 .. 2*NOUT-1
    int idx = t >> 1;                                  // idx = o*128 + b
    int g = t & 1;
    const float* p = g_part + g * 4 * NOUT + idx;
    float v0 = p[0 * NOUT], v1 = p[1 * NOUT], v2 = p[2 * NOUT], v3 = p[3 * NOUT];
    float v = (v0 + v1) + (v2 + v3);
    v += __shfl_xor_sync(0xffffffffu, v, 1);
    if (g == 0) {
        int o = idx >> 7, bi = idx & 127;
        out[bi * OUT_DIM + o] = bias[o] + v;
    }
}

extern "C" void kernel_launch(void* const* d_in, const int* in_sizes, int n_in,
                              void* d_out, int out_size) {
    const float* x     = (const float*)d_in[0];   // (128, 1024)
    const float* W     = (const float*)d_in[1];   // (512, 1024)
    const float* bias  = (const float*)d_in[2];   // (512,)
    const float* theta = (const float*)d_in[3];   // (512, 1024, 4)
    float* out = (float*)d_out;                   // (128, 512)

    (void)in_sizes; (void)n_in; (void)out_size;

    dim3 grid(OUT_DIM / OPB, NSPLIT, 2);   // (64, 8, 2) = 1024 blocks
    fbn_fused_kernel<<<grid, 256>>>(x, W, theta);

    reduce_kernel<<<(2 * NOUT) / 256, 256>>>(bias, out);
}